// round 3
// baseline (speedup 1.0000x reference)
#include <cuda_runtime.h>
#include <math.h>

// Problem constants
#define BATCH 16
#define LROWS 192   // 6*L rows of raw
#define AC    2046  // attributor columns
#define MC    2048  // M = A + 2
#define LD    32    // L (W_2 output dim)
#define TM    128   // columns of m per block in main kernel
#define NBLK  (MC / TM * BATCH)   // 256 main blocks

// Scratch (device globals; no allocation allowed)
__device__ float g_wq[BATCH][2][64];   // wq[b][n][j] = sum_l W2[j,l] * Key[b,l,col_n]
__device__ float g_wk[BATCH][2][64];   // wk[b][n][j] = sum_l W2[64+j,l] * Query[b,l,col_n]
__device__ float g_S[BATCH][2][64];    // S[b][n][j]  = sum_m reluV[j,m] * causal[b,m,col_n]
__device__ float g_A[2][MC];           // adj[m][col_n]
__device__ float g_P[2][MC];           // adj[m][col_n] * iw[m][col_n]
__device__ float g_R[2][MC];           // adj[col_n][m] * iw[col_n][m]
__device__ int   g_ctr;                // last-block-done counter

// ---------------------------------------------------------------------------
// Kernel 1 (prep): fuses the old setup + pack kernels + counter reset.
// grid 48 blocks x 128 threads.
//   blocks  0..31: per (b = blk>>1, n = blk&1) special-column wq/wk + zero g_S
//   blocks 32..47: pack 128 m-values each of adj/iw rows/cols; blk32/t0 resets ctr
// ---------------------------------------------------------------------------
__global__ __launch_bounds__(128) void prep_kernel(
    const float* __restrict__ user, const float* __restrict__ item,
    const float* __restrict__ W2,
    const float* __restrict__ adj, const float* __restrict__ iw) {

    int blk = blockIdx.x;
    int t = threadIdx.x;

    if (blk < 32) {
        int b = blk >> 1;
        int n = blk & 1;
        const float* src = (n ? item : user) + b * LROWS;
        __shared__ float xr[128];     // relu of rows 0..127 of the special column
        __shared__ float qs[32];      // Query[b, l, col_n]
        __shared__ float ks[32];      // Key[b, l, col_n]
        xr[t] = fmaxf(src[t], 0.0f);
        __syncthreads();
        if (t < 32) {
            float s = 0.0f;
            #pragma unroll
            for (int j = 0; j < 64; j++) s = fmaf(xr[j], W2[j * LD + t], s);
            qs[t] = s;
        } else if (t < 64) {
            int l = t - 32;
            float s = 0.0f;
            #pragma unroll
            for (int j = 0; j < 64; j++) s = fmaf(xr[64 + j], W2[(64 + j) * LD + l], s);
            ks[l] = s;
        }
        __syncthreads();
        if (t < 64) {
            float swq = 0.0f, swk = 0.0f;
            #pragma unroll
            for (int l = 0; l < 32; l++) {
                swq = fmaf(W2[t * LD + l],        ks[l], swq);
                swk = fmaf(W2[(64 + t) * LD + l], qs[l], swk);
            }
            g_wq[b][n][t] = swq;
            g_wk[b][n][t] = swk;
            g_S[b][n][t] = 0.0f;      // zero the accumulator every launch
        }
    } else {
        if (blk == 32 && t == 0) g_ctr = 0;
        int m = (blk - 32) * 128 + t;
        size_t row = (size_t)m * MC;
        float a0 = adj[row];
        float a1 = adj[row + (MC - 1)];
        g_A[0][m] = a0;
        g_A[1][m] = a1;
        g_P[0][m] = a0 * iw[row];
        g_P[1][m] = a1 * iw[row + (MC - 1)];
        g_R[0][m] = adj[m] * iw[m];
        size_t lastrow = (size_t)(MC - 1) * MC + m;
        g_R[1][m] = adj[lastrow] * iw[lastrow];
    }
}

// ---------------------------------------------------------------------------
// Kernel 2 (main): streaming pass. grid (mb=16, b=16), 384 threads.
//   group 0 (t 0..127):    Q-row dots  -> hq_sh
//   group 1 (t 128..255):  K-row dots  -> hk_sh
//   group 2 (t 256..383):  V-row relus -> Vsh
// then sigmoid-causal per (n, m), (j,n) x m reduction into g_S (atomics),
// then the LAST block to finish computes the 1024 outputs (fused epilogue).
// ---------------------------------------------------------------------------
__global__ __launch_bounds__(384) void main_kernel(
    const float* __restrict__ user, const float* __restrict__ item,
    const float* __restrict__ attributor, const float* __restrict__ W1,
    const float* __restrict__ W2, float* __restrict__ out) {

    __shared__ float Vsh[64][TM + 1];   // padded: bank-conflict-free row reads
    __shared__ float hq_sh[2][TM];
    __shared__ float hk_sh[2][TM];
    __shared__ float c_sh[2][TM];
    __shared__ float wq_sh[2][64];
    __shared__ float wk_sh[2][64];
    __shared__ int   islast;

    int b  = blockIdx.y;
    int mb = blockIdx.x;
    int t  = threadIdx.x;
    int group = t >> 7;          // 0,1,2
    int ml = t & (TM - 1);
    int m  = mb * TM + ml;

    if (t < 128) {
        ((float*)wq_sh)[t] = ((const float*)g_wq[b])[t];
        ((float*)wk_sh)[t] = ((const float*)g_wk[b])[t];
    }
    __syncthreads();

    bool isU = (m == 0), isI = (m == MC - 1);
    bool special = isU || isI;
    int mm1 = special ? 0 : (m - 1);    // safe offset (never deref OOB)
    const float* ap = attributor + ((size_t)b * LROWS + group * 64) * AC + mm1;
    const float* wp = W1 + (size_t)(group * 64) * AC + mm1;
    const float* up = (isU ? user : item) + b * LROWS + group * 64;

    if (group == 0) {
        float h0 = 0.0f, h1 = 0.0f;
        #pragma unroll 8
        for (int j = 0; j < 64; j++) {
            float x = special ? up[j] : ap[(size_t)j * AC] * wp[(size_t)j * AC];
            x = fmaxf(x, 0.0f);
            h0 = fmaf(x, wq_sh[0][j], h0);
            h1 = fmaf(x, wq_sh[1][j], h1);
        }
        hq_sh[0][ml] = h0;
        hq_sh[1][ml] = h1;
    } else if (group == 1) {
        float h0 = 0.0f, h1 = 0.0f;
        #pragma unroll 8
        for (int j = 0; j < 64; j++) {
            float x = special ? up[j] : ap[(size_t)j * AC] * wp[(size_t)j * AC];
            x = fmaxf(x, 0.0f);
            h0 = fmaf(x, wk_sh[0][j], h0);
            h1 = fmaf(x, wk_sh[1][j], h1);
        }
        hk_sh[0][ml] = h0;
        hk_sh[1][ml] = h1;
    } else {
        #pragma unroll 8
        for (int j = 0; j < 64; j++) {
            float x = special ? up[j] : ap[(size_t)j * AC] * wp[(size_t)j * AC];
            Vsh[j][ml] = fmaxf(x, 0.0f);
        }
    }
    __syncthreads();

    // causal[b, m, col_n] = sigmoid(h[m,n] - h[n,m]) * adj[m, col_n]
    if (t < 256) {
        int n  = t >> 7;
        int mm = t & (TM - 1);
        int mg = mb * TM + mm;
        float d = hq_sh[n][mm] * g_P[n][mg] - hk_sh[n][mm] * g_R[n][mg];
        c_sh[n][mm] = g_A[n][mg] / (1.0f + expf(-d));
    }
    __syncthreads();

    // S[b][n][j] += sum_mm Vsh[j][mm] * c_sh[n][mm]
    if (t < 128) {
        int n = t >> 6;
        int j = t & 63;
        float s = 0.0f;
        #pragma unroll 8
        for (int mm = 0; mm < TM; mm++)
            s = fmaf(Vsh[j][mm], c_sh[n][mm], s);
        atomicAdd(&g_S[b][n][j], s);
        __threadfence();           // make g_S atomics visible before counter bump
    }
    __syncthreads();

    // ---- fused epilogue: last block to finish computes the final projection ----
    if (t == 0) islast = (atomicAdd(&g_ctr, 1) == NBLK - 1);
    __syncthreads();
    if (islast) {
        // out[b, l, n] = sum_j W2[128+j, l] * S[b][n][j]; layout idx = b*64 + l*2 + n
        for (int idx = t; idx < BATCH * LD * 2; idx += 384) {
            int ob = idx >> 6;
            int l  = (idx >> 1) & 31;
            int n  = idx & 1;
            float s = 0.0f;
            #pragma unroll
            for (int j = 0; j < 64; j++)
                s = fmaf(W2[(128 + j) * LD + l], __ldcg(&g_S[ob][n][j]), s);
            out[idx] = s;
        }
    }
}

extern "C" void kernel_launch(void* const* d_in, const int* in_sizes, int n_in,
                              void* d_out, int out_size) {
    const float* user       = (const float*)d_in[0];
    const float* item       = (const float*)d_in[1];
    const float* attributor = (const float*)d_in[2];
    const float* adj        = (const float*)d_in[3];
    const float* iw         = (const float*)d_in[4];
    const float* W1         = (const float*)d_in[5];
    const float* W2         = (const float*)d_in[6];
    float* out = (float*)d_out;

    prep_kernel<<<48, 128>>>(user, item, W2, adj, iw);
    main_kernel<<<dim3(MC / TM, BATCH), 384>>>(user, item, attributor, W1, W2, out);
}

// round 4
// speedup vs baseline: 1.2317x; 1.2317x over previous
#include <cuda_runtime.h>
#include <math.h>

// Problem constants
#define BATCH 16
#define LROWS 192   // 6*L rows of raw
#define AC    2046  // attributor columns
#define MC    2048  // M = A + 2
#define LD    32    // L (W_2 output dim)
#define TM    128   // columns of m per block in main kernel

// Scratch (device globals; no allocation allowed)
__device__ float g_wq[BATCH][2][64];   // wq[b][n][j] = sum_l W2[j,l] * Key[b,l,col_n]
__device__ float g_wk[BATCH][2][64];   // wk[b][n][j] = sum_l W2[64+j,l] * Query[b,l,col_n]
__device__ float g_S[BATCH][2][64];    // S[b][n][j]  = sum_m reluV[j,m] * causal[b,m,col_n]
__device__ float g_A[2][MC];           // adj[m][col_n]
__device__ float g_P[2][MC];           // adj[m][col_n] * iw[m][col_n]
__device__ float g_R[2][MC];           // adj[col_n][m] * iw[col_n][m]

// ---------------------------------------------------------------------------
// Kernel 1 (prep): special-column wq/wk + adj/iw packing + g_S zeroing.
// grid 48 x 128 threads.
// ---------------------------------------------------------------------------
__global__ __launch_bounds__(128) void prep_kernel(
    const float* __restrict__ user, const float* __restrict__ item,
    const float* __restrict__ W2,
    const float* __restrict__ adj, const float* __restrict__ iw) {

    int blk = blockIdx.x;
    int t = threadIdx.x;

    if (blk < 32) {
        int b = blk >> 1;
        int n = blk & 1;
        const float* src = (n ? item : user) + b * LROWS;
        __shared__ float xr[128];
        __shared__ float qs[32];
        __shared__ float ks[32];
        xr[t] = fmaxf(src[t], 0.0f);
        __syncthreads();
        if (t < 32) {
            float s = 0.0f;
            #pragma unroll
            for (int j = 0; j < 64; j++) s = fmaf(xr[j], W2[j * LD + t], s);
            qs[t] = s;
        } else if (t < 64) {
            int l = t - 32;
            float s = 0.0f;
            #pragma unroll
            for (int j = 0; j < 64; j++) s = fmaf(xr[64 + j], W2[(64 + j) * LD + l], s);
            ks[l] = s;
        }
        __syncthreads();
        if (t < 64) {
            float swq = 0.0f, swk = 0.0f;
            #pragma unroll
            for (int l = 0; l < 32; l++) {
                swq = fmaf(W2[t * LD + l],        ks[l], swq);
                swk = fmaf(W2[(64 + t) * LD + l], qs[l], swk);
            }
            g_wq[b][n][t] = swq;
            g_wk[b][n][t] = swk;
            g_S[b][n][t] = 0.0f;      // zero the accumulator every launch
        }
    } else {
        int m = (blk - 32) * 128 + t;
        size_t row = (size_t)m * MC;
        float a0 = adj[row];
        float a1 = adj[row + (MC - 1)];
        g_A[0][m] = a0;
        g_A[1][m] = a1;
        g_P[0][m] = a0 * iw[row];
        g_P[1][m] = a1 * iw[row + (MC - 1)];
        g_R[0][m] = adj[m] * iw[m];
        size_t lastrow = (size_t)(MC - 1) * MC + m;
        g_R[1][m] = adj[lastrow] * iw[lastrow];
    }
}

// ---------------------------------------------------------------------------
// Kernel 2 (main): streaming pass. grid (mb=16, b=16), 384 threads.
// Explicit 8+8 register-batched loads for deep MLP.
// ---------------------------------------------------------------------------
__global__ __launch_bounds__(384) void main_kernel(
    const float* __restrict__ user, const float* __restrict__ item,
    const float* __restrict__ attributor, const float* __restrict__ W1) {

    __shared__ float Vsh[64][TM + 1];
    __shared__ float hq_sh[2][TM];
    __shared__ float hk_sh[2][TM];
    __shared__ float c_sh[2][TM];
    __shared__ float wq_sh[2][64];
    __shared__ float wk_sh[2][64];

    int b  = blockIdx.y;
    int mb = blockIdx.x;
    int t  = threadIdx.x;
    int group = t >> 7;          // 0,1,2
    int ml = t & (TM - 1);
    int m  = mb * TM + ml;

    if (t < 128) {
        ((float*)wq_sh)[t] = ((const float*)g_wq[b])[t];
        ((float*)wk_sh)[t] = ((const float*)g_wk[b])[t];
    }
    __syncthreads();

    bool isU = (m == 0), isI = (m == MC - 1);
    bool special = isU || isI;

    if (group < 2) {
        const float (*wsel)[64] = (group == 0) ? wq_sh : wk_sh;
        float h0 = 0.0f, h1 = 0.0f;
        if (special) {
            const float* up = (isU ? user : item) + b * LROWS + group * 64;
            #pragma unroll
            for (int j = 0; j < 64; j++) {
                float x = fmaxf(up[j], 0.0f);
                h0 = fmaf(x, wsel[0][j], h0);
                h1 = fmaf(x, wsel[1][j], h1);
            }
        } else {
            const float* ap = attributor + ((size_t)b * LROWS + group * 64) * AC + (m - 1);
            const float* wp = W1 + (size_t)(group * 64) * AC + (m - 1);
            #pragma unroll 2
            for (int jb = 0; jb < 64; jb += 8) {
                float av[8], wv[8];
                #pragma unroll
                for (int u = 0; u < 8; u++) av[u] = ap[(size_t)(jb + u) * AC];
                #pragma unroll
                for (int u = 0; u < 8; u++) wv[u] = wp[(size_t)(jb + u) * AC];
                #pragma unroll
                for (int u = 0; u < 8; u++) {
                    float x = fmaxf(av[u] * wv[u], 0.0f);
                    h0 = fmaf(x, wsel[0][jb + u], h0);
                    h1 = fmaf(x, wsel[1][jb + u], h1);
                }
            }
        }
        if (group == 0) { hq_sh[0][ml] = h0; hq_sh[1][ml] = h1; }
        else            { hk_sh[0][ml] = h0; hk_sh[1][ml] = h1; }
    } else {
        if (special) {
            const float* up = (isU ? user : item) + b * LROWS + 128;
            #pragma unroll
            for (int j = 0; j < 64; j++) Vsh[j][ml] = fmaxf(up[j], 0.0f);
        } else {
            const float* ap = attributor + ((size_t)b * LROWS + 128) * AC + (m - 1);
            const float* wp = W1 + (size_t)128 * AC + (m - 1);
            #pragma unroll 2
            for (int jb = 0; jb < 64; jb += 8) {
                float av[8], wv[8];
                #pragma unroll
                for (int u = 0; u < 8; u++) av[u] = ap[(size_t)(jb + u) * AC];
                #pragma unroll
                for (int u = 0; u < 8; u++) wv[u] = wp[(size_t)(jb + u) * AC];
                #pragma unroll
                for (int u = 0; u < 8; u++)
                    Vsh[jb + u][ml] = fmaxf(av[u] * wv[u], 0.0f);
            }
        }
    }
    __syncthreads();

    // causal[b, m, col_n] = sigmoid(h[m,n] - h[n,m]) * adj[m, col_n]
    if (t < 256) {
        int n  = t >> 7;
        int mm = t & (TM - 1);
        int mg = mb * TM + mm;
        float d = hq_sh[n][mm] * g_P[n][mg] - hk_sh[n][mm] * g_R[n][mg];
        c_sh[n][mm] = g_A[n][mg] / (1.0f + expf(-d));
    }
    __syncthreads();

    // S[b][n][j] += sum_mm Vsh[j][mm] * c_sh[n][mm]
    if (t < 128) {
        int n = t >> 6;
        int j = t & 63;
        float s = 0.0f;
        #pragma unroll 8
        for (int mm = 0; mm < TM; mm++)
            s = fmaf(Vsh[j][mm], c_sh[n][mm], s);
        atomicAdd(&g_S[b][n][j], s);
    }
}

// ---------------------------------------------------------------------------
// Kernel 3 (final): out[b, l, n] = sum_j W2[128+j, l] * S[b][n][j]
// 1 block x 1024 threads; everything staged in shared first (coalesced).
// ---------------------------------------------------------------------------
__global__ __launch_bounds__(1024) void final_kernel(
    const float* __restrict__ W2, float* __restrict__ out) {
    __shared__ float Ssh[BATCH * 2 * 64];   // 2048
    __shared__ float Wsh[64][LD];           // 2048
    int t = threadIdx.x;
    const float* Sg = (const float*)g_S;
    Ssh[t]        = Sg[t];
    Ssh[t + 1024] = Sg[t + 1024];
    {
        int j = t >> 5, l = t & 31;
        Wsh[j][l]      = W2[(128 + j) * LD + l];
        Wsh[j + 32][l] = W2[(160 + j) * LD + l];
    }
    __syncthreads();
    int b = t >> 6;
    int l = (t >> 1) & 31;
    int n = t & 1;
    const float* Sv = &Ssh[(b * 2 + n) * 64];
    float s = 0.0f;
    #pragma unroll
    for (int j = 0; j < 64; j++)
        s = fmaf(Wsh[j][l], Sv[j], s);
    out[t] = s;
}

extern "C" void kernel_launch(void* const* d_in, const int* in_sizes, int n_in,
                              void* d_out, int out_size) {
    const float* user       = (const float*)d_in[0];
    const float* item       = (const float*)d_in[1];
    const float* attributor = (const float*)d_in[2];
    const float* adj        = (const float*)d_in[3];
    const float* iw         = (const float*)d_in[4];
    const float* W1         = (const float*)d_in[5];
    const float* W2         = (const float*)d_in[6];
    float* out = (float*)d_out;

    prep_kernel<<<48, 128>>>(user, item, W2, adj, iw);
    main_kernel<<<dim3(MC / TM, BATCH), 384>>>(user, item, attributor, W1);
    final_kernel<<<1, 1024>>>(W2, out);
}